// round 14
// baseline (speedup 1.0000x reference)
#include <cuda_runtime.h>
#include <cstdint>

#define BATCH  32
#define SEQ    512
#define LAB    64
#define START_ 61
#define STOP_  62
#define CH     32

#define FMA2(d,a,b,c)  asm("fma.rn.f32x2 %0, %1, %2, %3;" : "=l"(d) : "l"(a), "l"(b), "l"(c))
#define ADD2(d,a,b)    asm("add.rn.f32x2 %0, %1, %2;"     : "=l"(d) : "l"(a), "l"(b))
#define PACK2(d,lo,hi) asm("mov.b64 %0, {%1, %2};"        : "=l"(d) : "f"(lo), "f"(hi))
#define UNPACK2(lo,hi,s) asm("mov.b64 {%0, %1}, %2;"      : "=f"(lo), "=f"(hi) : "l"(s))
#define CPA(dst,src) asm volatile("cp.async.cg.shared.global [%0], [%1], 16;\n" :: "r"(dst), "l"(src))
#define CPC() asm volatile("cp.async.commit_group;\n")
#define CPW1() asm volatile("cp.async.wait_group 1;\n")
#define CPW0() asm volatile("cp.async.wait_group 0;\n")
#define SYNCW() __syncwarp()

// per-warp chunk prefetch: 32 lanes x 16B x 16 = 8 KB
#define PREFETCH(cc) do {                                                        \
    const float* _src = encb + (size_t)(cc) * CH * LAB + lane * 4;               \
    uint32_t _dst = (uint32_t)__cvta_generic_to_shared(&esh[(cc) & 1][lane*4]);  \
    _Pragma("unroll")                                                            \
    for (int _i = 0; _i < 16; ++_i)                                              \
        CPA(_dst + _i * 512, _src + _i * 128);                                   \
    CPC();                                                                       \
} while (0)

// dual-column 64-wide dot: 16 broadcast LDS.128 shared by both columns,
// 64 FMA2 (2 accums per column), produces qA, qB and w0 (for p[0] scale)
#define DOT2(PV, QA, QB)                                                      \
    ulonglong2 w0 = (PV)[0];                                                  \
    unsigned long long aA0 = 0, aA1 = 0, aB0 = 0, aB1 = 0;                    \
    FMA2(aA0, w0.x, EA[0], aA0); FMA2(aB0, w0.x, EB[0], aB0);                 \
    FMA2(aA1, w0.y, EA[1], aA1); FMA2(aB1, w0.y, EB[1], aB1);                 \
    _Pragma("unroll")                                                         \
    for (int _kk = 1; _kk < 16; ++_kk) {                                      \
        ulonglong2 _v = (PV)[_kk];                                            \
        FMA2(aA0, _v.x, EA[2*_kk],   aA0); FMA2(aB0, _v.x, EB[2*_kk],   aB0); \
        FMA2(aA1, _v.y, EA[2*_kk+1], aA1); FMA2(aB1, _v.y, EB[2*_kk+1], aB1); \
    }                                                                         \
    unsigned long long sA, sBv;                                               \
    ADD2(sA, aA0, aA1); ADD2(sBv, aB0, aB1);                                  \
    float _alo, _ahi, _blo, _bhi;                                             \
    UNPACK2(_alo, _ahi, sA); UNPACK2(_blo, _bhi, sBv);                        \
    float QA = _alo + _ahi;                                                   \
    float QB = _blo + _bhi

// chains per batch: 0=x(seg1) 1=f2 2=f3 3=f4 4=g2 5=g3 6=g4 7=y(seg5)
__device__ float g_v[8][BATCH][LAB];
__device__ float g_lab[2][BATCH];
__device__ int   g_mi8[8][BATCH];
__device__ int   g_cnt[BATCH];     // never reset; +2 per launch; parity -> combiner

__global__ __launch_bounds__(128, 1)
void crf_fused_kernel(const float* __restrict__ enc,   // [B,S,L]
                      const float* __restrict__ T,     // [L,L]
                      const int*   __restrict__ lens,  // [B]
                      const int*   __restrict__ tags,  // [B,S]
                      float*       __restrict__ out)   // [2*B]
{
    __shared__ __align__(16) float e_sh4[4][2][CH * LAB];  // per-warp enc buffers
    __shared__ __align__(16) float p_sh4[4][2][LAB];       // per-warp state
    __shared__ float lw[4];
    __shared__ float du[14];
    __shared__ int win_sh;

    const int tid  = threadIdx.x;
    const int wid  = tid >> 5;            // chain slot in block (SMSP wid%4)
    const int lane = tid & 31;

    const int b = blockIdx.x >> 1;
    const int h = blockIdx.x & 1;         // 0: fwd chains 0-3, 1: bwd chains 4-7
    const int k = 4 * h + wid;            // chain id 0..7
    const int len = lens[b];
    const int n   = len - 1;
    int sB[6];
    #pragma unroll
    for (int i = 0; i <= 5; ++i) sB[i] = (i * n) / 5;
    const float* encb = enc + (size_t)b * SEQ * LAB;
    const int*   tagb = tags + b * SEQ;

    float (*esh)[CH * LAB] = e_sh4[wid];
    float (*psh)[LAB]      = p_sh4[wid];

    const int jA = lane;                  // this thread's two columns
    const int jB = lane + 32;

    int Mi = 0;
    int par_out;

    if (h == 0) {
        // ---- FORWARD chains: p <- D_u E^T p over seg k+1 = (sB[k], sB[k+1]] ----
        const int t0 = sB[k] + 1;
        const int t1 = sB[k + 1];

        unsigned long long EA[32], EB[32];   // E columns jA, jB (rows 0..63)
        #pragma unroll
        for (int kk = 0; kk < 32; ++kk) {
            float a0 = expf(T[(2 * kk)     * LAB + jA]);
            float a1 = expf(T[(2 * kk + 1) * LAB + jA]);
            float b0 = expf(T[(2 * kk)     * LAB + jB]);
            float b1 = expf(T[(2 * kk + 1) * LAB + jB]);
            PACK2(EA[kk], a0, a1);
            PACK2(EB[kk], b0, b1);
        }

        const int c0 = t0 >> 5, c1 = t1 >> 5;
        PREFETCH(c0);
        if (c0 < c1) { PREFETCH(c0 + 1); CPW1(); } else CPW0();
        SYNCW();
        if (k == 0) {
            psh[0][jA] = expf(T[START_ * LAB + jA] + esh[0][jA]);
            psh[0][jB] = expf(T[START_ * LAB + jB] + esh[0][jB]);
        } else {
            psh[(t0 - 1) & 1][jA] = 1.0f;
            psh[(t0 - 1) & 1][jB] = 1.0f;
        }
        SYNCW();

        int t = t0;
        for (int c = c0; c <= c1; ++c) {
            if (c > c0) {
                if (c < c1) { PREFETCH(c + 1); CPW1(); } else CPW0();
                SYNCW();
            }
            const float* eb = esh[c & 1];
            const int ttend = min((c + 1) * CH - 1, t1);
            #pragma unroll 2
            for (; t <= ttend; ++t) {
                const float* pp = &psh[(t - 1) & 1][0];
                const ulonglong2* pv = reinterpret_cast<const ulonglong2*>(pp);
                float uA = __expf(eb[(t - c * CH) * LAB + jA]);
                float uB = __expf(eb[(t - c * CH) * LAB + jB]);
                DOT2(pv, qA, qB);
                unsigned int p0b = (unsigned int)w0.x;      // p[0], broadcast-uniform
                int   e0 = (int)((p0b >> 23) & 255u) - 127;
                float sc = __int_as_float((127 - e0) << 23);
                Mi += e0;
                psh[t & 1][jA] = qA * uA * sc;
                psh[t & 1][jB] = qB * uB * sc;
                SYNCW();
            }
        }
        par_out = t1 & 1;
    } else {
        // ---- BACKWARD chains: w <- D_u E w over seg sg = (sB[sg-1], sB[sg]] ----
        const int sg = k - 2;                          // 2,3,4,5
        const int s_init = sB[sg];
        const int s_end  = sB[sg - 1];
        const int s1 = s_init - 1, s0 = s_end;

        unsigned long long EA[32], EB[32];   // E rows jA, jB (cols 0..63)
        #pragma unroll
        for (int kk = 0; kk < 32; ++kk) {
            float a0 = expf(T[jA * LAB + 2 * kk]);
            float a1 = expf(T[jA * LAB + 2 * kk + 1]);
            float b0 = expf(T[jB * LAB + 2 * kk]);
            float b1 = expf(T[jB * LAB + 2 * kk + 1]);
            PACK2(EA[kk], a0, a1);
            PACK2(EB[kk], b0, b1);
        }

        const int chi = s1 >> 5, clo = s0 >> 5;
        PREFETCH(chi);
        if (chi > clo) PREFETCH(chi - 1);
        {
            float uiA = __expf(encb[(size_t)s_init * LAB + jA]);
            float uiB = __expf(encb[(size_t)s_init * LAB + jB]);
            if (sg == 5) {
                uiA *= expf(T[jA * LAB + STOP_]);      // y: c * u_n
                uiB *= expf(T[jB * LAB + STOP_]);
            }
            psh[(s1 + 1) & 1][jA] = uiA;
            psh[(s1 + 1) & 1][jB] = uiB;
        }
        if (chi > clo) CPW1(); else CPW0();
        SYNCW();

        int s = s1;
        for (int c = chi; c >= clo; --c) {
            if (c < chi) {
                if (c > clo) { PREFETCH(c - 1); CPW1(); } else CPW0();
                SYNCW();
            }
            const float* eb = esh[c & 1];
            const int slo = max(s0, c * CH);
            #pragma unroll 2
            for (; s >= slo; --s) {
                const float* pp = &psh[(s + 1) & 1][0];
                const ulonglong2* pv = reinterpret_cast<const ulonglong2*>(pp);
                float uA = __expf(eb[(s - c * CH) * LAB + jA]);
                float uB = __expf(eb[(s - c * CH) * LAB + jB]);
                DOT2(pv, qA, qB);
                unsigned int p0b = (unsigned int)w0.x;
                int   e0 = (int)((p0b >> 23) & 255u) - 127;
                float sc = __int_as_float((127 - e0) << 23);
                Mi += e0;
                float usA = (s == s0) ? sc : uA * sc;  // boundary: apply E only
                float usB = (s == s0) ? sc : uB * sc;
                psh[s & 1][jA] = qA * usA;
                psh[s & 1][jB] = qB * usB;
                SYNCW();
            }
        }
        par_out = s0 & 1;
    }

    g_v[k][b][jA] = psh[par_out][jA];
    g_v[k][b][jB] = psh[par_out][jB];
    if (lane == 0) g_mi8[k][b] = Mi;
    __syncthreads();                       // all 4 chains of this block done

    // ---- labeled partial for this block's half of [1, n] ----
    {
        const int lo = 1 + (h * n) / 2;
        const int hi = 1 + ((h + 1) * n) / 2;
        float lsum = 0.0f;
        for (int t = lo + tid; t < hi; t += 128) {
            int tg = tagb[t], tp = tagb[t - 1];
            lsum += T[tp * LAB + tg] + encb[(size_t)t * LAB + tg];
        }
        #pragma unroll
        for (int m = 16; m; m >>= 1)
            lsum += __shfl_xor_sync(0xffffffffu, lsum, m);
        if (lane == 0) lw[wid] = lsum;
        __syncthreads();
        if (tid == 0) g_lab[h][b] = lw[0] + lw[1] + lw[2] + lw[3];
    }

    // ---- last-arriver combine ----
    __threadfence();
    __syncthreads();
    if (tid == 0) {
        int old = atomicAdd(&g_cnt[b], 1);
        win_sh = (old & 1);                // second of the pair this launch
    }
    __syncthreads();
    if (win_sh) {
        float d1 = 0, d2 = 0, d3 = 0, d4 = 0, d5 = 0, d6 = 0, d7 = 0;
        if (tid < LAB) {
            float xv  = __ldcg(&g_v[0][b][tid]);
            float f2v = __ldcg(&g_v[1][b][tid]);
            float f3v = __ldcg(&g_v[2][b][tid]);
            float f4v = __ldcg(&g_v[3][b][tid]);
            float g2v = __ldcg(&g_v[4][b][tid]);
            float g3v = __ldcg(&g_v[5][b][tid]);
            float g4v = __ldcg(&g_v[6][b][tid]);
            float yv  = __ldcg(&g_v[7][b][tid]);
            d1 = yv  * f4v;    // c^T M5 f4
            d2 = g4v * f3v;
            d3 = g3v * f2v;
            d4 = g2v * xv;     // g2^T M1 p0
            d5 = f2v; d6 = f3v; d7 = f4v;
        }
        #pragma unroll
        for (int m = 16; m; m >>= 1) {
            d1 += __shfl_xor_sync(0xffffffffu, d1, m);
            d2 += __shfl_xor_sync(0xffffffffu, d2, m);
            d3 += __shfl_xor_sync(0xffffffffu, d3, m);
            d4 += __shfl_xor_sync(0xffffffffu, d4, m);
            d5 += __shfl_xor_sync(0xffffffffu, d5, m);
            d6 += __shfl_xor_sync(0xffffffffu, d6, m);
            d7 += __shfl_xor_sync(0xffffffffu, d7, m);
        }
        if (tid == 0) {
            du[0]=d1; du[1]=d2; du[2]=d3; du[3]=d4; du[4]=d5; du[5]=d6; du[6]=d7;
        }
        if (tid == 32) {
            du[7]=d1; du[8]=d2; du[9]=d3; du[10]=d4; du[11]=d5; du[12]=d6; du[13]=d7;
        }
        __syncthreads();
        if (tid == 0) {
            float D1 = du[0] + du[7];
            float D2 = du[1] + du[8];
            float D3 = du[2] + du[9];
            float D4 = du[3] + du[10];
            float S2 = du[4] + du[11];
            float S3 = du[5] + du[12];
            float S4 = du[6] + du[13];
            int mtot = __ldcg(&g_mi8[0][b]) + __ldcg(&g_mi8[4][b])
                     + __ldcg(&g_mi8[5][b]) + __ldcg(&g_mi8[6][b])
                     + __ldcg(&g_mi8[7][b]);
            double lg = (double)logf(D1) + (double)logf(D2)
                      + (double)logf(D3) + (double)logf(D4)
                      - (double)logf(S2) - (double)logf(S3) - (double)logf(S4);
            out[b] = (float)((double)mtot * 0.6931471805599453 + lg);

            int t0g = tagb[0];
            int eg  = tagb[len - 1];
            out[BATCH + b] = __ldcg(&g_lab[0][b]) + __ldcg(&g_lab[1][b])
                           + T[START_ * LAB + t0g] + encb[t0g]
                           + T[eg * LAB + STOP_];
        }
    }
}

extern "C" void kernel_launch(void* const* d_in, const int* in_sizes, int n_in,
                              void* d_out, int out_size)
{
    const float* enc  = (const float*)d_in[0];   // encoder_scores [32,512,64]
    const float* T    = (const float*)d_in[1];   // transition [64,64]
    const int*   lens = (const int*)  d_in[2];   // word_seq_lens [32]
    const int*   tags = (const int*)  d_in[3];   // tags [32,512]
    float* out = (float*)d_out;                  // [64]: unlabeled(32) ++ labeled(32)

    crf_fused_kernel<<<2 * BATCH, 128>>>(enc, T, lens, tags, out);
}

// round 15
// speedup vs baseline: 1.1370x; 1.1370x over previous
#include <cuda_runtime.h>
#include <cstdint>

#define BATCH  32
#define SEQ    512
#define LAB    64
#define START_ 61
#define STOP_  62
#define CH     32

#define FMA2(d,a,b,c)  asm("fma.rn.f32x2 %0, %1, %2, %3;" : "=l"(d) : "l"(a), "l"(b), "l"(c))
#define ADD2(d,a,b)    asm("add.rn.f32x2 %0, %1, %2;"     : "=l"(d) : "l"(a), "l"(b))
#define PACK2(d,lo,hi) asm("mov.b64 %0, {%1, %2};"        : "=l"(d) : "f"(lo), "f"(hi))
#define UNPACK2(lo,hi,s) asm("mov.b64 {%0, %1}, %2;"      : "=f"(lo), "=f"(hi) : "l"(s))
#define CPA(dst,src) asm volatile("cp.async.cg.shared.global [%0], [%1], 16;\n" :: "r"(dst), "l"(src))
#define CPC() asm volatile("cp.async.commit_group;\n")
#define CPW1() asm volatile("cp.async.wait_group 1;\n")
#define CPW0() asm volatile("cp.async.wait_group 0;\n")

// 64-thread chunk prefetch: 8 KB = 8 x (64 thr x 16 B)
#define PREFETCH(cc) do {                                                       \
    const float* _src = encb + (size_t)(cc) * CH * LAB + tid * 4;               \
    uint32_t _dst = (uint32_t)__cvta_generic_to_shared(&e_sh[(cc) & 1][tid*4]); \
    CPA(_dst,        _src);         CPA(_dst + 1024, _src + 256);               \
    CPA(_dst + 2048, _src + 512);   CPA(_dst + 3072, _src + 768);               \
    CPA(_dst + 4096, _src + 1024);  CPA(_dst + 5120, _src + 1280);              \
    CPA(_dst + 6144, _src + 1536);  CPA(_dst + 7168, _src + 1792);              \
    CPC();                                                                      \
} while (0)

// full 64-wide dot per thread: 16 broadcast LDS.128 + 32 FMA2 + tree
#define DOT64(PV, Q)                                                          \
    ulonglong2 w0 = (PV)[0],  w1 = (PV)[1],  w2 = (PV)[2],  w3 = (PV)[3];     \
    ulonglong2 w4 = (PV)[4],  w5 = (PV)[5],  w6 = (PV)[6],  w7 = (PV)[7];     \
    ulonglong2 w8 = (PV)[8],  w9 = (PV)[9],  wA = (PV)[10], wB = (PV)[11];    \
    ulonglong2 wC = (PV)[12], wD = (PV)[13], wE = (PV)[14], wF = (PV)[15];    \
    unsigned long long a0 = 0, a1 = 0, a2 = 0, a3 = 0;                        \
    FMA2(a0, w0.x, E2[ 0], a0); FMA2(a1, w0.y, E2[ 1], a1);                   \
    FMA2(a2, w1.x, E2[ 2], a2); FMA2(a3, w1.y, E2[ 3], a3);                   \
    FMA2(a0, w2.x, E2[ 4], a0); FMA2(a1, w2.y, E2[ 5], a1);                   \
    FMA2(a2, w3.x, E2[ 6], a2); FMA2(a3, w3.y, E2[ 7], a3);                   \
    FMA2(a0, w4.x, E2[ 8], a0); FMA2(a1, w4.y, E2[ 9], a1);                   \
    FMA2(a2, w5.x, E2[10], a2); FMA2(a3, w5.y, E2[11], a3);                   \
    FMA2(a0, w6.x, E2[12], a0); FMA2(a1, w6.y, E2[13], a1);                   \
    FMA2(a2, w7.x, E2[14], a2); FMA2(a3, w7.y, E2[15], a3);                   \
    FMA2(a0, w8.x, E2[16], a0); FMA2(a1, w8.y, E2[17], a1);                   \
    FMA2(a2, w9.x, E2[18], a2); FMA2(a3, w9.y, E2[19], a3);                   \
    FMA2(a0, wA.x, E2[20], a0); FMA2(a1, wA.y, E2[21], a1);                   \
    FMA2(a2, wB.x, E2[22], a2); FMA2(a3, wB.y, E2[23], a3);                   \
    FMA2(a0, wC.x, E2[24], a0); FMA2(a1, wC.y, E2[25], a1);                   \
    FMA2(a2, wD.x, E2[26], a2); FMA2(a3, wD.y, E2[27], a3);                   \
    FMA2(a0, wE.x, E2[28], a0); FMA2(a1, wE.y, E2[29], a1);                   \
    FMA2(a2, wF.x, E2[30], a2); FMA2(a3, wF.y, E2[31], a3);                   \
    unsigned long long s01, s23, sT;                                          \
    ADD2(s01, a0, a1); ADD2(s23, a2, a3); ADD2(sT, s01, s23);                 \
    float qlo, qhi; UNPACK2(qlo, qhi, sT);                                    \
    float Q = qlo + qhi

// chains per batch: 0 = x (seg1 fwd), 1 = f probe (seg2 fwd),
//                   2 = g probe (seg2 bwd), 3 = y (seg3 bwd)
__device__ float g_v[4][BATCH][LAB];
__device__ float g_lab[4][BATCH];
__device__ int   g_mi4[4][BATCH];
__device__ int   g_cnt[BATCH];     // never reset; +4 per launch; (old&3)==3 -> combiner

__global__ __launch_bounds__(64, 1)
void crf_fused_kernel(const float* __restrict__ enc,   // [B,S,L]
                      const float* __restrict__ T,     // [L,L]
                      const int*   __restrict__ lens,  // [B]
                      const int*   __restrict__ tags,  // [B,S]
                      float*       __restrict__ out)   // [2*B]
{
    __shared__ __align__(16) float e_sh[2][CH * LAB];
    __shared__ __align__(16) float p_sh[2][LAB];
    __shared__ float lw[2];
    __shared__ float du[6];
    __shared__ int win_sh;

    const int tid = threadIdx.x;
    const int b   = blockIdx.x >> 2;
    const int k   = blockIdx.x & 3;       // chain id 0..3
    const int len = lens[b];
    const int n   = len - 1;
    int sB[4];
    #pragma unroll
    for (int i = 0; i <= 3; ++i) sB[i] = (i * n) / 3;
    const float* encb = enc + (size_t)b * SEQ * LAB;
    const int*   tagb = tags + b * SEQ;

    int Mi = 0;
    int par_out;

    if (k <= 1) {
        // ---- FORWARD chains: p <- D_u E^T p over seg k+1 = (sB[k], sB[k+1]] ----
        const int t0 = sB[k] + 1;
        const int t1 = sB[k + 1];

        unsigned long long E2[32];                     // E column tid, all 64 rows
        #pragma unroll
        for (int kk = 0; kk < 32; ++kk) {
            float lo = expf(T[(2 * kk)     * LAB + tid]);
            float hi = expf(T[(2 * kk + 1) * LAB + tid]);
            PACK2(E2[kk], lo, hi);
        }

        const int c0 = t0 >> 5, c1 = t1 >> 5;
        PREFETCH(c0);
        if (c0 < c1) { PREFETCH(c0 + 1); CPW1(); } else CPW0();
        __syncthreads();
        if (k == 0) p_sh[0][tid] = expf(T[START_ * LAB + tid] + e_sh[0][tid]);
        else        p_sh[(t0 - 1) & 1][tid] = 1.0f;   // probe: ones
        __syncthreads();

        int t = t0;
        for (int c = c0; c <= c1; ++c) {
            if (c > c0) {
                if (c < c1) { PREFETCH(c + 1); CPW1(); } else CPW0();
                __syncthreads();
            }
            const float* eb = e_sh[c & 1];
            const int ttend = min((c + 1) * CH - 1, t1);
            #pragma unroll 4
            for (; t <= ttend; ++t) {
                const float* pp = &p_sh[(t - 1) & 1][0];
                const ulonglong2* pv = reinterpret_cast<const ulonglong2*>(pp);
                float u  = __expf(eb[(t - c * CH) * LAB + tid]);
                DOT64(pv, q);
                unsigned int p0b = (unsigned int)w0.x;     // p[0], broadcast-uniform
                int   e0 = (int)((p0b >> 23) & 255u) - 127;
                float sc = __int_as_float((127 - e0) << 23);
                Mi += e0;
                p_sh[t & 1][tid] = q * u * sc;
                __syncthreads();
            }
        }
        par_out = t1 & 1;
    } else {
        // ---- BACKWARD chains: w <- D_u E w over seg k = (sB[k-1], sB[k]] ----
        // k=2: g probe (init ones -> w_sb = u_sb). k=3: y (init c*u_n). Last step E-only.
        const int s_init = sB[k];
        const int s_end  = sB[k - 1];
        const int s1 = s_init - 1, s0 = s_end;

        unsigned long long E2[32];                     // E row tid, all 64 cols
        #pragma unroll
        for (int kk = 0; kk < 32; ++kk) {
            float lo = expf(T[tid * LAB + 2 * kk]);
            float hi = expf(T[tid * LAB + 2 * kk + 1]);
            PACK2(E2[kk], lo, hi);
        }

        const int chi = s1 >> 5, clo = s0 >> 5;
        PREFETCH(chi);
        if (chi > clo) PREFETCH(chi - 1);
        {
            float uinit = __expf(encb[(size_t)s_init * LAB + tid]);
            if (k == 3) uinit *= expf(T[tid * LAB + STOP_]);   // y: c * u_n
            p_sh[(s1 + 1) & 1][tid] = uinit;
        }
        if (chi > clo) CPW1(); else CPW0();
        __syncthreads();

        int s = s1;
        for (int c = chi; c >= clo; --c) {
            if (c < chi) {
                if (c > clo) { PREFETCH(c - 1); CPW1(); } else CPW0();
                __syncthreads();
            }
            const float* eb = e_sh[c & 1];
            const int slo = max(s0, c * CH);
            #pragma unroll 4
            for (; s >= slo; --s) {
                const float* pp = &p_sh[(s + 1) & 1][0];
                const ulonglong2* pv = reinterpret_cast<const ulonglong2*>(pp);
                float u  = __expf(eb[(s - c * CH) * LAB + tid]);
                DOT64(pv, q);
                unsigned int p0b = (unsigned int)w0.x;
                int   e0 = (int)((p0b >> 23) & 255u) - 127;
                float sc = __int_as_float((127 - e0) << 23);
                Mi += e0;
                float us = (s == s0) ? sc : u * sc;    // boundary: apply E only
                p_sh[s & 1][tid] = q * us;
                __syncthreads();
            }
        }
        par_out = s0 & 1;
    }

    g_v[k][b][tid] = p_sh[par_out][tid];
    if (tid == 0) g_mi4[k][b] = Mi;
    __syncthreads();

    // ---- labeled partial for this block's quarter of [1, n] ----
    {
        const int lo = 1 + (k * n) / 4;
        const int hi = 1 + ((k + 1) * n) / 4;
        float lsum = 0.0f;
        for (int t = lo + tid; t < hi; t += 64) {
            int tg = tagb[t], tp = tagb[t - 1];
            lsum += T[tp * LAB + tg] + encb[(size_t)t * LAB + tg];
        }
        #pragma unroll
        for (int m = 16; m; m >>= 1)
            lsum += __shfl_xor_sync(0xffffffffu, lsum, m);
        if ((tid & 31) == 0) lw[tid >> 5] = lsum;
        __syncthreads();
        if (tid == 0) g_lab[k][b] = lw[0] + lw[1];
    }

    // ---- last-arriver combine ----
    __threadfence();
    __syncthreads();
    if (tid == 0) {
        int old = atomicAdd(&g_cnt[b], 1);
        win_sh = ((old & 3) == 3);
    }
    __syncthreads();
    if (win_sh) {
        float xv = __ldcg(&g_v[0][b][tid]);
        float fv = __ldcg(&g_v[1][b][tid]);
        float gv = __ldcg(&g_v[2][b][tid]);
        float yv = __ldcg(&g_v[3][b][tid]);
        float d1 = yv * fv;                // c^T M3 f
        float d2 = gv * xv;                // g^T M1 p0
        float d3 = fv;                     // 1^T f
        #pragma unroll
        for (int m = 16; m; m >>= 1) {
            d1 += __shfl_xor_sync(0xffffffffu, d1, m);
            d2 += __shfl_xor_sync(0xffffffffu, d2, m);
            d3 += __shfl_xor_sync(0xffffffffu, d3, m);
        }
        if (tid == 0)  { du[0] = d1; du[1] = d2; du[2] = d3; }
        if (tid == 32) { du[3] = d1; du[4] = d2; du[5] = d3; }
        __syncthreads();
        if (tid == 0) {
            float D1 = du[0] + du[3];
            float D2 = du[1] + du[4];
            float D3 = du[2] + du[5];
            int mtot = __ldcg(&g_mi4[0][b]) + __ldcg(&g_mi4[2][b])
                     + __ldcg(&g_mi4[3][b]);          // f-probe exponent cancels
            out[b] = (float)((double)mtot * 0.6931471805599453
                             + (double)(logf(D1) + logf(D2) - logf(D3)));

            int t0g = tagb[0];
            int eg  = tagb[len - 1];
            out[BATCH + b] = __ldcg(&g_lab[0][b]) + __ldcg(&g_lab[1][b])
                           + __ldcg(&g_lab[2][b]) + __ldcg(&g_lab[3][b])
                           + T[START_ * LAB + t0g] + encb[t0g]
                           + T[eg * LAB + STOP_];
        }
    }
}

extern "C" void kernel_launch(void* const* d_in, const int* in_sizes, int n_in,
                              void* d_out, int out_size)
{
    const float* enc  = (const float*)d_in[0];   // encoder_scores [32,512,64]
    const float* T    = (const float*)d_in[1];   // transition [64,64]
    const int*   lens = (const int*)  d_in[2];   // word_seq_lens [32]
    const int*   tags = (const int*)  d_in[3];   // tags [32,512]
    float* out = (float*)d_out;                  // [64]: unlabeled(32) ++ labeled(32)

    crf_fused_kernel<<<4 * BATCH, 64>>>(enc, T, lens, tags, out);
}

// round 16
// speedup vs baseline: 1.1643x; 1.0240x over previous
#include <cuda_runtime.h>
#include <cstdint>

#define BATCH  32
#define SEQ    512
#define LAB    64
#define START_ 61
#define STOP_  62
#define CH     32

#define FMA2(d,a,b,c)  asm("fma.rn.f32x2 %0, %1, %2, %3;" : "=l"(d) : "l"(a), "l"(b), "l"(c))
#define ADD2(d,a,b)    asm("add.rn.f32x2 %0, %1, %2;"     : "=l"(d) : "l"(a), "l"(b))
#define PACK2(d,lo,hi) asm("mov.b64 %0, {%1, %2};"        : "=l"(d) : "f"(lo), "f"(hi))
#define UNPACK2(lo,hi,s) asm("mov.b64 {%0, %1}, %2;"      : "=f"(lo), "=f"(hi) : "l"(s))
#define CPA(dst,src) asm volatile("cp.async.cg.shared.global [%0], [%1], 16;\n" :: "r"(dst), "l"(src))
#define CPC() asm volatile("cp.async.commit_group;\n")
#define CPW1() asm volatile("cp.async.wait_group 1;\n")
#define CPW0() asm volatile("cp.async.wait_group 0;\n")

// per-WARP chunk prefetch: 8 KB = 16 x (32 lanes x 16 B), into this warp's buffer
#define PREFETCH(cc) do {                                                         \
    const float* _src = encb + (size_t)(cc) * CH * LAB + lane * 4;                \
    uint32_t _dst = (uint32_t)__cvta_generic_to_shared(&esh[(cc) & 1][lane * 4]); \
    _Pragma("unroll")                                                             \
    for (int _i = 0; _i < 16; ++_i)                                               \
        CPA(_dst + _i * 512, _src + _i * 128);                                    \
    CPC();                                                                        \
} while (0)

// dual-column 64-wide dot, p loaded in 4-temp groups (low reg pressure).
// Produces qA (col jA), qB (col jB) and p0b (bits of p[0]).
#define DOT2(PP, QA, QB, P0B)                                                   \
    const ulonglong2* pv = reinterpret_cast<const ulonglong2*>(PP);             \
    unsigned long long c0 = 0, c1 = 0, c2 = 0, c3 = 0;                          \
    unsigned int P0B;                                                           \
    _Pragma("unroll")                                                           \
    for (int q4 = 0; q4 < 4; ++q4) {                                            \
        ulonglong2 va = pv[4 * q4 + 0];                                         \
        ulonglong2 vb = pv[4 * q4 + 1];                                         \
        ulonglong2 vc = pv[4 * q4 + 2];                                         \
        ulonglong2 vd = pv[4 * q4 + 3];                                         \
        if (q4 == 0) P0B = (unsigned int)va.x;                                  \
        FMA2(c0, va.x, EA[8 * q4 + 0], c0); FMA2(c2, va.x, EB[8 * q4 + 0], c2); \
        FMA2(c1, va.y, EA[8 * q4 + 1], c1); FMA2(c3, va.y, EB[8 * q4 + 1], c3); \
        FMA2(c0, vb.x, EA[8 * q4 + 2], c0); FMA2(c2, vb.x, EB[8 * q4 + 2], c2); \
        FMA2(c1, vb.y, EA[8 * q4 + 3], c1); FMA2(c3, vb.y, EB[8 * q4 + 3], c3); \
        FMA2(c0, vc.x, EA[8 * q4 + 4], c0); FMA2(c2, vc.x, EB[8 * q4 + 4], c2); \
        FMA2(c1, vc.y, EA[8 * q4 + 5], c1); FMA2(c3, vc.y, EB[8 * q4 + 5], c3); \
        FMA2(c0, vd.x, EA[8 * q4 + 6], c0); FMA2(c2, vd.x, EB[8 * q4 + 6], c2); \
        FMA2(c1, vd.y, EA[8 * q4 + 7], c1); FMA2(c3, vd.y, EB[8 * q4 + 7], c3); \
    }                                                                           \
    unsigned long long sA, sB_;                                                 \
    ADD2(sA, c0, c1); ADD2(sB_, c2, c3);                                        \
    float _al, _ah, _bl, _bh;                                                   \
    UNPACK2(_al, _ah, sA); UNPACK2(_bl, _bh, sB_);                              \
    float QA = _al + _ah;                                                       \
    float QB = _bl + _bh

// chains per batch: 0=x(seg1) 1=f2 2=f3 3=f4 4=g2 5=g3 6=g4 7=y(seg5)
__device__ float g_v[8][BATCH][LAB];
__device__ float g_lab[4][BATCH];
__device__ int   g_mi8[8][BATCH];
__device__ int   g_cnt[BATCH];     // never reset; +4 per launch; (old&3)==3 -> combiner

__global__ __launch_bounds__(64, 1)
void crf_fused_kernel(const float* __restrict__ enc,   // [B,S,L]
                      const float* __restrict__ T,     // [L,L]
                      const int*   __restrict__ lens,  // [B]
                      const int*   __restrict__ tags,  // [B,S]
                      float*       __restrict__ out)   // [2*B]
{
    __shared__ __align__(16) float e_shw[2][2][CH * LAB];  // [warp][buf] enc slices
    __shared__ __align__(16) float p_shw[2][2][LAB];       // [warp][buf] state
    __shared__ float lw[2];
    __shared__ float du[14];
    __shared__ int win_sh;

    const int tid  = threadIdx.x;
    const int wid  = tid >> 5;            // warp = chain slot
    const int lane = tid & 31;

    const int b    = blockIdx.x >> 2;
    const int pair = blockIdx.x & 3;
    const int k    = (wid == 0) ? pair : 4 + pair;   // chain id 0..7
    const int len  = lens[b];
    const int n    = len - 1;
    int sB[6];
    #pragma unroll
    for (int i = 0; i <= 5; ++i) sB[i] = (i * n) / 5;
    const float* encb = enc + (size_t)b * SEQ * LAB;
    const int*   tagb = tags + b * SEQ;

    float (*esh)[CH * LAB] = e_shw[wid];
    float (*psh)[LAB]      = p_shw[wid];

    const int jA = lane;                  // this thread's two columns/rows
    const int jB = lane + 32;

    int Mi = 0;
    int par_out;

    if (wid == 0) {
        // ---- FORWARD chain k = pair: p <- D_u E^T p over (sB[k], sB[k+1]] ----
        const int t0 = sB[k] + 1;
        const int t1 = sB[k + 1];
        const int c0i = t0 >> 5, c1i = t1 >> 5;
        PREFETCH(c0i);
        if (c0i < c1i) PREFETCH(c0i + 1);

        unsigned long long EA[32], EB[32];   // E columns jA, jB (rows 0..63)
        #pragma unroll
        for (int kk = 0; kk < 32; ++kk) {
            float a0 = __expf(T[(2 * kk)     * LAB + jA]);
            float a1 = __expf(T[(2 * kk + 1) * LAB + jA]);
            float b0 = __expf(T[(2 * kk)     * LAB + jB]);
            float b1 = __expf(T[(2 * kk + 1) * LAB + jB]);
            PACK2(EA[kk], a0, a1);
            PACK2(EB[kk], b0, b1);
        }

        if (c0i < c1i) CPW1(); else CPW0();
        __syncwarp();
        if (k == 0) {
            psh[0][jA] = __expf(T[START_ * LAB + jA] + esh[0][jA]);
            psh[0][jB] = __expf(T[START_ * LAB + jB] + esh[0][jB]);
        } else {
            psh[(t0 - 1) & 1][jA] = 1.0f;
            psh[(t0 - 1) & 1][jB] = 1.0f;
        }
        __syncwarp();

        int t = t0;
        for (int c = c0i; c <= c1i; ++c) {
            if (c > c0i) {
                if (c < c1i) { PREFETCH(c + 1); CPW1(); } else CPW0();
                __syncwarp();
            }
            const float* eb = esh[c & 1];
            const int ttend = min((c + 1) * CH - 1, t1);
            #pragma unroll 1
            for (; t <= ttend; ++t) {
                const float* pp = &psh[(t - 1) & 1][0];
                const int ro = (t - c * CH) * LAB;
                float uA = __expf(eb[ro + jA]);
                float uB = __expf(eb[ro + jB]);
                DOT2(pp, qA, qB, p0b);
                int   e0 = (int)((p0b >> 23) & 255u) - 127;
                float sc = __int_as_float((127 - e0) << 23);
                Mi += e0;
                psh[t & 1][jA] = qA * uA * sc;
                psh[t & 1][jB] = qB * uB * sc;
                __syncwarp();
            }
        }
        par_out = t1 & 1;
    } else {
        // ---- BACKWARD chain k = 4+pair: w <- D_u E w over seg sg=(k-2) ----
        const int sg = k - 2;                          // 2,3,4,5
        const int s_init = sB[sg];
        const int s_end  = sB[sg - 1];
        const int s1 = s_init - 1, s0 = s_end;
        const int chi = s1 >> 5, clo = s0 >> 5;
        PREFETCH(chi);
        if (chi > clo) PREFETCH(chi - 1);

        unsigned long long EA[32], EB[32];   // E rows jA, jB (cols 0..63)
        #pragma unroll
        for (int kk = 0; kk < 32; ++kk) {
            float a0 = __expf(T[jA * LAB + 2 * kk]);
            float a1 = __expf(T[jA * LAB + 2 * kk + 1]);
            float b0 = __expf(T[jB * LAB + 2 * kk]);
            float b1 = __expf(T[jB * LAB + 2 * kk + 1]);
            PACK2(EA[kk], a0, a1);
            PACK2(EB[kk], b0, b1);
        }

        {
            float uiA = __expf(encb[(size_t)s_init * LAB + jA]);
            float uiB = __expf(encb[(size_t)s_init * LAB + jB]);
            if (sg == 5) {
                uiA *= __expf(T[jA * LAB + STOP_]);    // y: c * u_n
                uiB *= __expf(T[jB * LAB + STOP_]);
            }
            psh[(s1 + 1) & 1][jA] = uiA;
            psh[(s1 + 1) & 1][jB] = uiB;
        }
        if (chi > clo) CPW1(); else CPW0();
        __syncwarp();

        int s = s1;
        for (int c = chi; c >= clo; --c) {
            if (c < chi) {
                if (c > clo) { PREFETCH(c - 1); CPW1(); } else CPW0();
                __syncwarp();
            }
            const float* eb = esh[c & 1];
            const int slo = max(s0, c * CH);
            #pragma unroll 1
            for (; s >= slo; --s) {
                const float* pp = &psh[(s + 1) & 1][0];
                const int ro = (s - c * CH) * LAB;
                float uA = __expf(eb[ro + jA]);
                float uB = __expf(eb[ro + jB]);
                DOT2(pp, qA, qB, p0b);
                int   e0 = (int)((p0b >> 23) & 255u) - 127;
                float sc = __int_as_float((127 - e0) << 23);
                Mi += e0;
                float usA = (s == s0) ? sc : uA * sc;  // boundary: apply E only
                float usB = (s == s0) ? sc : uB * sc;
                psh[s & 1][jA] = qA * usA;
                psh[s & 1][jB] = qB * usB;
                __syncwarp();
            }
        }
        par_out = s0 & 1;
    }

    g_v[k][b][jA] = psh[par_out][jA];
    g_v[k][b][jB] = psh[par_out][jB];
    if (lane == 0) g_mi8[k][b] = Mi;
    __syncthreads();                       // both chains of this block done

    // ---- labeled partial for this block's quarter of [1, n] ----
    {
        const int lo = 1 + (pair * n) / 4;
        const int hi = 1 + ((pair + 1) * n) / 4;
        float lsum = 0.0f;
        for (int t = lo + tid; t < hi; t += 64) {
            int tg = tagb[t], tp = tagb[t - 1];
            lsum += T[tp * LAB + tg] + encb[(size_t)t * LAB + tg];
        }
        #pragma unroll
        for (int m = 16; m; m >>= 1)
            lsum += __shfl_xor_sync(0xffffffffu, lsum, m);
        if (lane == 0) lw[wid] = lsum;
        __syncthreads();
        if (tid == 0) g_lab[pair][b] = lw[0] + lw[1];
    }

    // ---- last-arriver combine ----
    __threadfence();
    __syncthreads();
    if (tid == 0) {
        int old = atomicAdd(&g_cnt[b], 1);
        win_sh = ((old & 3) == 3);
    }
    __syncthreads();
    if (win_sh) {
        float xv  = __ldcg(&g_v[0][b][tid]);
        float f2v = __ldcg(&g_v[1][b][tid]);
        float f3v = __ldcg(&g_v[2][b][tid]);
        float f4v = __ldcg(&g_v[3][b][tid]);
        float g2v = __ldcg(&g_v[4][b][tid]);
        float g3v = __ldcg(&g_v[5][b][tid]);
        float g4v = __ldcg(&g_v[6][b][tid]);
        float yv  = __ldcg(&g_v[7][b][tid]);
        float d1 = yv  * f4v;    // c^T M5 f4
        float d2 = g4v * f3v;
        float d3 = g3v * f2v;
        float d4 = g2v * xv;     // g2^T M1 p0
        float d5 = f2v, d6 = f3v, d7 = f4v;
        #pragma unroll
        for (int m = 16; m; m >>= 1) {
            d1 += __shfl_xor_sync(0xffffffffu, d1, m);
            d2 += __shfl_xor_sync(0xffffffffu, d2, m);
            d3 += __shfl_xor_sync(0xffffffffu, d3, m);
            d4 += __shfl_xor_sync(0xffffffffu, d4, m);
            d5 += __shfl_xor_sync(0xffffffffu, d5, m);
            d6 += __shfl_xor_sync(0xffffffffu, d6, m);
            d7 += __shfl_xor_sync(0xffffffffu, d7, m);
        }
        if (tid == 0) {
            du[0]=d1; du[1]=d2; du[2]=d3; du[3]=d4; du[4]=d5; du[5]=d6; du[6]=d7;
        }
        if (tid == 32) {
            du[7]=d1; du[8]=d2; du[9]=d3; du[10]=d4; du[11]=d5; du[12]=d6; du[13]=d7;
        }
        __syncthreads();
        if (tid == 0) {
            float D1 = du[0] + du[7];
            float D2 = du[1] + du[8];
            float D3 = du[2] + du[9];
            float D4 = du[3] + du[10];
            float S2 = du[4] + du[11];
            float S3 = du[5] + du[12];
            float S4 = du[6] + du[13];
            int mtot = __ldcg(&g_mi8[0][b]) + __ldcg(&g_mi8[4][b])
                     + __ldcg(&g_mi8[5][b]) + __ldcg(&g_mi8[6][b])
                     + __ldcg(&g_mi8[7][b]);
            double lg = (double)logf(D1) + (double)logf(D2)
                      + (double)logf(D3) + (double)logf(D4)
                      - (double)logf(S2) - (double)logf(S3) - (double)logf(S4);
            out[b] = (float)((double)mtot * 0.6931471805599453 + lg);

            int t0g = tagb[0];
            int eg  = tagb[len - 1];
            out[BATCH + b] = __ldcg(&g_lab[0][b]) + __ldcg(&g_lab[1][b])
                           + __ldcg(&g_lab[2][b]) + __ldcg(&g_lab[3][b])
                           + T[START_ * LAB + t0g] + encb[t0g]
                           + T[eg * LAB + STOP_];
        }
    }
}

extern "C" void kernel_launch(void* const* d_in, const int* in_sizes, int n_in,
                              void* d_out, int out_size)
{
    const float* enc  = (const float*)d_in[0];   // encoder_scores [32,512,64]
    const float* T    = (const float*)d_in[1];   // transition [64,64]
    const int*   lens = (const int*)  d_in[2];   // word_seq_lens [32]
    const int*   tags = (const int*)  d_in[3];   // tags [32,512]
    float* out = (float*)d_out;                  // [64]: unlabeled(32) ++ labeled(32)

    crf_fused_kernel<<<4 * BATCH, 64>>>(enc, T, lens, tags, out);
}